// round 2
// baseline (speedup 1.0000x reference)
#include <cuda_runtime.h>
#include <math.h>

// ---------------------------------------------------------------------------
// InvariantPolynomial: out = SILU_CST * sum_e x_left[oi[e]] * x_right[e] * f(|pos_e|)
// where f(d) = sum_j silu( (emb(d) @ W1/sqrt(20))_j ) * (rowsum(W2)/sqrt(30))_j
// sh[:, :1] == 1 identically (l=0 SH), so the SH block is dead code.
// Strategy: build f as an 8192-entry lookup table per launch; main pass is
// memory-bound streaming + L2-resident gather.
// ---------------------------------------------------------------------------

#define TABLE_N 8192
#define D_MAX   5.25f          // all 20 gaussian emb underflow to 0 in fp32 for d >= ~4.8
#define NQ_PTS  100000         // quadrature intervals (100001 points), matches reference

__device__ float  g_tab[TABLE_N];
__device__ float  g_cst;
__device__ double g_sum;

// ---------------------------------------------------------------------------
// Setup: blocks 0..31 build the f(d) table; block 32 computes the silu
// normalize2mom constant via the reference's trapezoid quadrature and zeroes
// the accumulator. Independent work -> one kernel.
// ---------------------------------------------------------------------------
__global__ void setup_kernel(const float* __restrict__ W1,
                             const float* __restrict__ W2) {
    if (blockIdx.x == 32) {
        if (threadIdx.x == 0) g_sum = 0.0;
        __shared__ double red[256];
        float acc = 0.f;
        for (int i = threadIdx.x; i <= NQ_PTS; i += 256) {
            float z   = (float)(-12.0 + 2.4e-4 * (double)i);
            float s   = z / (1.0f + __expf(-z));                       // silu(z)
            float phi = 0.3989422804014327f * __expf(-0.5f * z * z);   // N(0,1) pdf
            float f   = s * s * phi;
            if (i == 0 || i == NQ_PTS) f *= 0.5f;                      // trapezoid ends
            acc += f;
        }
        red[threadIdx.x] = (double)acc;
        __syncthreads();
        for (int s = 128; s > 0; s >>= 1) {
            if (threadIdx.x < s) red[threadIdx.x] += red[threadIdx.x + s];
            __syncthreads();
        }
        if (threadIdx.x == 0) {
            double integral = (24.0 / 100000.0) * red[0];
            g_cst = (float)(1.0 / sqrt(integral));                     // ~1.679
        }
        return;
    }

    // ---- table blocks ----
    __shared__ float sW1[600];   // W1 [20,30] row-major
    __shared__ float sW2s[30];   // rowsum(W2)/sqrt(30)
    for (int i = threadIdx.x; i < 600; i += 256) sW1[i] = W1[i];
    if (threadIdx.x < 30) {
        float s = 0.f;
        #pragma unroll
        for (int c = 0; c < 5; c++) s += W2[threadIdx.x * 5 + c];
        sW2s[threadIdx.x] = s * 0.18257418583505536f;   // 1/sqrt(30)
    }
    __syncthreads();

    int   i = blockIdx.x * 256 + threadIdx.x;           // 0..8191
    float d = (float)i * (D_MAX / (float)(TABLE_N - 1));

    // emb_k = exp(-((d - v_k)/step)^2)/1.12,  v_k = 3.5*(k+1)/21, step = 3.5/21
    float e[20];
    #pragma unroll
    for (int k = 0; k < 20; k++) {
        float v    = (float)(k + 1) * (3.5f / 21.0f);
        float diff = (d - v) * (21.0f / 3.5f);
        e[k] = __expf(-diff * diff) * (1.0f / 1.12f);
    }

    float pre[30];
    #pragma unroll
    for (int j = 0; j < 30; j++) pre[j] = 0.f;
    #pragma unroll
    for (int k = 0; k < 20; k++) {
        #pragma unroll
        for (int j = 0; j < 30; j++) pre[j] = fmaf(e[k], sW1[k * 30 + j], pre[j]);
    }

    float f = 0.f;
    #pragma unroll
    for (int j = 0; j < 30; j++) {
        float p   = pre[j] * 0.22360679774997896f;      // 1/sqrt(20)
        float sil = p / (1.0f + __expf(-p));            // silu (cst applied at the end)
        f = fmaf(sil, sW2s[j], f);
    }
    g_tab[i] = f;
}

// ---------------------------------------------------------------------------
// Main pass: one float per edge accumulated into a per-block double atomic.
// ---------------------------------------------------------------------------
__device__ __forceinline__ float edge_term(float x, float y, float z,
                                           float w, int id,
                                           const float* __restrict__ xleft) {
    float d  = sqrtf(fmaf(x, x, fmaf(y, y, z * z)));
    float ft = fminf(d * ((float)(TABLE_N - 1) / D_MAX), (float)(TABLE_N - 1));
    int   i  = min((int)ft, TABLE_N - 2);
    float f0 = g_tab[i];
    float f1 = g_tab[i + 1];
    float f  = fmaf(ft - (float)i, f1 - f0, f0);        // == 0 for d near/above D_MAX
    return f * w * __ldg(&xleft[id]);
}

__global__ void __launch_bounds__(256)
main_kernel(const float4* __restrict__ pos4,
            const float4* __restrict__ xr4,
            const int4*   __restrict__ idx4,
            const float*  __restrict__ xleft,
            const float*  __restrict__ pos,
            const float*  __restrict__ xr,
            const int*    __restrict__ idx,
            int nq, int E) {
    int t = blockIdx.x * blockDim.x + threadIdx.x;
    float local = 0.f;
    if (t < nq) {
        float4 a = pos4[3 * t];
        float4 b = pos4[3 * t + 1];
        float4 c = pos4[3 * t + 2];
        float4 w = xr4[t];
        int4  id = idx4[t];
        local += edge_term(a.x, a.y, a.z, w.x, id.x, xleft);
        local += edge_term(a.w, b.x, b.y, w.y, id.y, xleft);
        local += edge_term(b.z, b.w, c.x, w.z, id.z, xleft);
        local += edge_term(c.y, c.z, c.w, w.w, id.w, xleft);
    }
    if (t == 0) {   // tail edges (E not divisible by 4)
        for (int e2 = nq * 4; e2 < E; e2++)
            local += edge_term(pos[3 * e2], pos[3 * e2 + 1], pos[3 * e2 + 2],
                               xr[e2], idx[e2], xleft);
    }

    // block reduction -> one double atomic per block
    #pragma unroll
    for (int o = 16; o > 0; o >>= 1)
        local += __shfl_down_sync(0xffffffffu, local, o);
    __shared__ float warpsum[8];
    int lane = threadIdx.x & 31, wid = threadIdx.x >> 5;
    if (lane == 0) warpsum[wid] = local;
    __syncthreads();
    if (wid == 0) {
        float v = (lane < 8) ? warpsum[lane] : 0.f;
        #pragma unroll
        for (int o = 4; o > 0; o >>= 1)
            v += __shfl_down_sync(0xffffffffu, v, o);
        if (lane == 0) atomicAdd(&g_sum, (double)v);
    }
}

__global__ void final_kernel(float* __restrict__ out) {
    out[0] = (float)(g_sum * (double)g_cst);
}

// ---------------------------------------------------------------------------
extern "C" void kernel_launch(void* const* d_in, const int* in_sizes, int n_in,
                              void* d_out, int out_size) {
    const float* pos = (const float*)d_in[0];   // [E,3]
    const float* xr  = (const float*)d_in[1];   // [E,1]
    const float* xl  = (const float*)d_in[2];   // [N,1]
    const float* W1  = (const float*)d_in[3];   // [20,30]
    const float* W2  = (const float*)d_in[4];   // [30,5]
    const int*   oi  = (const int*)d_in[5];     // [E]

    int E  = in_sizes[1];          // x_right element count == E
    if (E < 0) E = 0;
    int nq = E / 4;

    setup_kernel<<<33, 256>>>(W1, W2);

    int nb = (nq + 255) / 256;
    if (nb < 1) nb = 1;
    main_kernel<<<nb, 256>>>((const float4*)pos, (const float4*)xr,
                             (const int4*)oi, xl, pos, xr, oi, nq, E);

    final_kernel<<<1, 1>>>((float*)d_out);
}

// round 3
// speedup vs baseline: 1.5444x; 1.5444x over previous
#include <cuda_runtime.h>
#include <math.h>

// ---------------------------------------------------------------------------
// InvariantPolynomial: out = SILU_CST * sum_e x_left[oi[e]] * x_right[e] * f(|pos_e|)
// f(d) = sum_j silu( (emb(d) @ W1/sqrt(20))_j ) * (rowsum(W2)/sqrt(30))_j
// sh[:, :1] == 1 identically (l=0 SH) -> SH block is dead code.
// R2 lesson: the serial 100001-pt quadrature on one block cost 41us.
// Now: one quadrature point per thread, per-block partial arrays (no atomics,
// no re-zeroing -> graph-replay safe and bit-deterministic).
// ---------------------------------------------------------------------------

#define TABLE_N  8192
#define D_MAX    5.25f         // all 20 gaussian emb underflow to 0 in fp32 for d >= ~4.8
#define NQ_PTS   100000        // quadrature intervals (100001 points), matches reference
#define NQB      391           // 391*256 = 100096 >= 100001 quadrature threads
#define TBLB     32            // 32*256 = 8192 table threads
#define MAXMB    8192          // max main-kernel blocks (grid-stride beyond)

__device__ float  g_tab[TABLE_N];
__device__ double g_qpart[NQB];
__device__ double g_mpart[MAXMB];

// ---------------------------------------------------------------------------
// Setup: blocks [0, NQB) quadrature (1 point/thread); blocks [NQB, NQB+32) table.
// ---------------------------------------------------------------------------
__global__ void __launch_bounds__(256) setup_kernel(const float* __restrict__ W1,
                                                    const float* __restrict__ W2) {
    if (blockIdx.x < NQB) {
        int   i = blockIdx.x * 256 + threadIdx.x;        // quadrature point index
        float v = 0.f;
        if (i <= NQ_PTS) {
            float z   = (float)(-12.0 + 2.4e-4 * (double)i);
            float s   = z / (1.0f + __expf(-z));                     // silu(z)
            float phi = 0.3989422804014327f * __expf(-0.5f * z * z); // N(0,1) pdf
            v = s * s * phi;
            if (i == 0 || i == NQ_PTS) v *= 0.5f;                    // trapezoid ends
        }
        __shared__ double red[256];
        red[threadIdx.x] = (double)v;
        __syncthreads();
        #pragma unroll
        for (int s = 128; s > 0; s >>= 1) {
            if (threadIdx.x < s) red[threadIdx.x] += red[threadIdx.x + s];
            __syncthreads();
        }
        if (threadIdx.x == 0) g_qpart[blockIdx.x] = red[0];
        return;
    }

    // ---- table blocks ----
    __shared__ float sW1[600];   // W1 [20,30] row-major
    __shared__ float sW2s[30];   // rowsum(W2)/sqrt(30)
    for (int i = threadIdx.x; i < 600; i += 256) sW1[i] = W1[i];
    if (threadIdx.x < 30) {
        float s = 0.f;
        #pragma unroll
        for (int c = 0; c < 5; c++) s += W2[threadIdx.x * 5 + c];
        sW2s[threadIdx.x] = s * 0.18257418583505536f;   // 1/sqrt(30)
    }
    __syncthreads();

    int   i = (blockIdx.x - NQB) * 256 + threadIdx.x;   // 0..8191
    float d = (float)i * (D_MAX / (float)(TABLE_N - 1));

    // emb_k = exp(-((d - v_k)/step)^2)/1.12,  v_k = 3.5*(k+1)/21, step = 3.5/21
    float e[20];
    #pragma unroll
    for (int k = 0; k < 20; k++) {
        float vk   = (float)(k + 1) * (3.5f / 21.0f);
        float diff = (d - vk) * (21.0f / 3.5f);
        e[k] = __expf(-diff * diff) * (1.0f / 1.12f);
    }

    float pre[30];
    #pragma unroll
    for (int j = 0; j < 30; j++) pre[j] = 0.f;
    #pragma unroll
    for (int k = 0; k < 20; k++) {
        #pragma unroll
        for (int j = 0; j < 30; j++) pre[j] = fmaf(e[k], sW1[k * 30 + j], pre[j]);
    }

    float f = 0.f;
    #pragma unroll
    for (int j = 0; j < 30; j++) {
        float p   = pre[j] * 0.22360679774997896f;      // 1/sqrt(20)
        float sil = p / (1.0f + __expf(-p));            // silu (cst applied at the end)
        f = fmaf(sil, sW2s[j], f);
    }
    g_tab[i] = f;
}

// ---------------------------------------------------------------------------
// Main pass: one float per edge, per-block double partial (deterministic).
// ---------------------------------------------------------------------------
__device__ __forceinline__ float edge_term(float x, float y, float z,
                                           float w, int id,
                                           const float* __restrict__ xleft) {
    float d  = sqrtf(fmaf(x, x, fmaf(y, y, z * z)));
    float ft = fminf(d * ((float)(TABLE_N - 1) / D_MAX), (float)(TABLE_N - 1));
    int   i  = min((int)ft, TABLE_N - 2);
    float f0 = g_tab[i];
    float f1 = g_tab[i + 1];
    float f  = fmaf(ft - (float)i, f1 - f0, f0);        // == 0 for d near/above D_MAX
    return f * w * __ldg(&xleft[id]);
}

__global__ void __launch_bounds__(256)
main_kernel(const float4* __restrict__ pos4,
            const float4* __restrict__ xr4,
            const int4*   __restrict__ idx4,
            const float*  __restrict__ xleft,
            const float*  __restrict__ pos,
            const float*  __restrict__ xr,
            const int*    __restrict__ idx,
            int nq, int E) {
    float local = 0.f;
    for (int t = blockIdx.x * blockDim.x + threadIdx.x; t < nq;
         t += gridDim.x * blockDim.x) {
        float4 a = pos4[3 * t];
        float4 b = pos4[3 * t + 1];
        float4 c = pos4[3 * t + 2];
        float4 w = xr4[t];
        int4  id = idx4[t];
        local += edge_term(a.x, a.y, a.z, w.x, id.x, xleft);
        local += edge_term(a.w, b.x, b.y, w.y, id.y, xleft);
        local += edge_term(b.z, b.w, c.x, w.z, id.z, xleft);
        local += edge_term(c.y, c.z, c.w, w.w, id.w, xleft);
    }
    if (blockIdx.x == 0 && threadIdx.x == 0) {   // tail edges (E % 4)
        for (int e2 = nq * 4; e2 < E; e2++)
            local += edge_term(pos[3 * e2], pos[3 * e2 + 1], pos[3 * e2 + 2],
                               xr[e2], idx[e2], xleft);
    }

    // block reduction -> one double partial per block
    #pragma unroll
    for (int o = 16; o > 0; o >>= 1)
        local += __shfl_down_sync(0xffffffffu, local, o);
    __shared__ float warpsum[8];
    int lane = threadIdx.x & 31, wid = threadIdx.x >> 5;
    if (lane == 0) warpsum[wid] = local;
    __syncthreads();
    if (wid == 0) {
        float v = (lane < 8) ? warpsum[lane] : 0.f;
        #pragma unroll
        for (int o = 4; o > 0; o >>= 1)
            v += __shfl_down_sync(0xffffffffu, v, o);
        if (lane == 0) g_mpart[blockIdx.x] = (double)v;
    }
}

// ---------------------------------------------------------------------------
// Final: fixed-order parallel sums of both partial arrays, then scale.
// ---------------------------------------------------------------------------
__global__ void __launch_bounds__(256) final_kernel(float* __restrict__ out, int nmb) {
    __shared__ double redm[256], redq[256];
    double m = 0.0, q = 0.0;
    for (int i = threadIdx.x; i < nmb; i += 256) m += g_mpart[i];
    for (int i = threadIdx.x; i < NQB; i += 256) q += g_qpart[i];
    redm[threadIdx.x] = m;
    redq[threadIdx.x] = q;
    __syncthreads();
    #pragma unroll
    for (int s = 128; s > 0; s >>= 1) {
        if (threadIdx.x < s) {
            redm[threadIdx.x] += redm[threadIdx.x + s];
            redq[threadIdx.x] += redq[threadIdx.x + s];
        }
        __syncthreads();
    }
    if (threadIdx.x == 0) {
        double integral = (24.0 / 100000.0) * redq[0];
        double cst = 1.0 / sqrt(integral);               // ~1.679 (silu normalize2mom)
        out[0] = (float)(redm[0] * cst);
    }
}

// ---------------------------------------------------------------------------
extern "C" void kernel_launch(void* const* d_in, const int* in_sizes, int n_in,
                              void* d_out, int out_size) {
    const float* pos = (const float*)d_in[0];   // [E,3]
    const float* xr  = (const float*)d_in[1];   // [E,1]
    const float* xl  = (const float*)d_in[2];   // [N,1]
    const float* W1  = (const float*)d_in[3];   // [20,30]
    const float* W2  = (const float*)d_in[4];   // [30,5]
    const int*   oi  = (const int*)d_in[5];     // [E]

    int E = in_sizes[1];          // x_right element count == E
    if (E < 0) E = 0;
    int nq = E / 4;

    setup_kernel<<<NQB + TBLB, 256>>>(W1, W2);

    int nb = (nq + 255) / 256;
    if (nb < 1) nb = 1;
    if (nb > MAXMB) nb = MAXMB;
    main_kernel<<<nb, 256>>>((const float4*)pos, (const float4*)xr,
                             (const int4*)oi, xl, pos, xr, oi, nq, E);

    final_kernel<<<1, 256>>>((float*)d_out, nb);
}

// round 4
// speedup vs baseline: 2.2919x; 1.4840x over previous
#include <cuda_runtime.h>
#include <math.h>

// ---------------------------------------------------------------------------
// InvariantPolynomial: out = SILU_CST * sum_e x_left[oi[e]] * x_right[e] * f(|pos_e|)
// f(d) = sum_j silu( (emb(d) @ W1/sqrt(20))_j ) * (rowsum(W2)/sqrt(30))_j
// sh[:, :1] == 1 identically (l=0 SH) -> SH block is dead code.
// R3 lesson: setup was 18.8us -- IEEE float divides + FP64 quadrature.
// Now: __fdividef everywhere, fp32 8193-pt trapezoid (exact pow2 step),
// float tree reductions, FP64 only in the 1-block final kernel.
// ---------------------------------------------------------------------------

#define TABLE_N  8192
#define D_MAX    5.25f         // all 20 gaussian emb underflow to 0 in fp32 for d >= ~4.8
#define QN       8192          // quadrature intervals (8193 points), err ~8e-6 rel
#define QH       (24.0f / 8192.0f)   // exactly representable step
#define SETUP_BT 128           // setup block size
#define NQB      64            // 64*128 = 8192 quad threads (+1 handled at i==QN)
#define TBLB     64            // 64*128 = 8192 table threads
#define MAXMB    8192          // max main-kernel blocks (grid-stride beyond)

__device__ float g_tab[TABLE_N];
__device__ float g_qpart[NQB + 1];     // +1: the i==QN endpoint partial
__device__ double g_mpart[MAXMB];

// ---------------------------------------------------------------------------
// Setup: blocks [0, NQB) quadrature (1 point/thread); blocks [NQB, NQB+TBLB)
// table (1 entry/thread). All fp32, no IEEE divides.
// ---------------------------------------------------------------------------
__device__ __forceinline__ float silu_f(float p) {
    return __fdividef(p, 1.0f + __expf(-p));
}

__global__ void __launch_bounds__(SETUP_BT) setup_kernel(const float* __restrict__ W1,
                                                         const float* __restrict__ W2) {
    if (blockIdx.x < NQB) {
        int   i = blockIdx.x * SETUP_BT + threadIdx.x;   // 0..8191 (i==QN below)
        float z   = fmaf((float)i, QH, -12.0f);
        float s   = silu_f(z);
        float phi = 0.3989422804014327f * __expf(-0.5f * z * z);
        float v   = s * s * phi;
        if (i == 0) v *= 0.5f;                           // trapezoid left end
        __shared__ float red[SETUP_BT];
        red[threadIdx.x] = v;
        __syncthreads();
        #pragma unroll
        for (int st = SETUP_BT / 2; st > 0; st >>= 1) {
            if (threadIdx.x < st) red[threadIdx.x] += red[threadIdx.x + st];
            __syncthreads();
        }
        if (threadIdx.x == 0) g_qpart[blockIdx.x] = red[0];
        if (blockIdx.x == 0 && threadIdx.x == 0) {
            // right endpoint i == QN (z = +12), weight 0.5
            float z2   = 12.0f;
            float s2   = silu_f(z2);
            float phi2 = 0.3989422804014327f * __expf(-0.5f * z2 * z2);
            g_qpart[NQB] = 0.5f * s2 * s2 * phi2;
        }
        return;
    }

    // ---- table blocks ----
    __shared__ float sW1[600];   // W1 [20,30] row-major
    __shared__ float sW2s[30];   // rowsum(W2)/sqrt(30)
    for (int i = threadIdx.x; i < 600; i += SETUP_BT) sW1[i] = W1[i];
    if (threadIdx.x < 30) {
        float s = 0.f;
        #pragma unroll
        for (int c = 0; c < 5; c++) s += W2[threadIdx.x * 5 + c];
        sW2s[threadIdx.x] = s * 0.18257418583505536f;   // 1/sqrt(30)
    }
    __syncthreads();

    int   i = (blockIdx.x - NQB) * SETUP_BT + threadIdx.x;   // 0..8191
    float d = (float)i * (D_MAX / (float)(TABLE_N - 1));

    // emb_k = exp(-((d - v_k)/step)^2)/1.12,  v_k = 3.5*(k+1)/21, step = 3.5/21
    float e[20];
    #pragma unroll
    for (int k = 0; k < 20; k++) {
        float vk   = (float)(k + 1) * (3.5f / 21.0f);
        float diff = (d - vk) * (21.0f / 3.5f);
        e[k] = __expf(-diff * diff) * (1.0f / 1.12f);
    }

    float pre[30];
    #pragma unroll
    for (int j = 0; j < 30; j++) pre[j] = 0.f;
    #pragma unroll
    for (int k = 0; k < 20; k++) {
        #pragma unroll
        for (int j = 0; j < 30; j++) pre[j] = fmaf(e[k], sW1[k * 30 + j], pre[j]);
    }

    float f = 0.f;
    #pragma unroll
    for (int j = 0; j < 30; j++) {
        float p = pre[j] * 0.22360679774997896f;        // 1/sqrt(20)
        f = fmaf(silu_f(p), sW2s[j], f);                // cst applied at the end
    }
    g_tab[i] = f;
}

// ---------------------------------------------------------------------------
// Main pass: one float per edge, per-block double partial (deterministic).
// ---------------------------------------------------------------------------
__device__ __forceinline__ float edge_term(float x, float y, float z,
                                           float w, int id,
                                           const float* __restrict__ xleft) {
    float d  = sqrtf(fmaf(x, x, fmaf(y, y, z * z)));
    float ft = fminf(d * ((float)(TABLE_N - 1) / D_MAX), (float)(TABLE_N - 1));
    int   i  = min((int)ft, TABLE_N - 2);
    float f0 = g_tab[i];
    float f1 = g_tab[i + 1];
    float f  = fmaf(ft - (float)i, f1 - f0, f0);        // == 0 for d near/above D_MAX
    return f * w * __ldg(&xleft[id]);
}

__global__ void __launch_bounds__(256)
main_kernel(const float4* __restrict__ pos4,
            const float4* __restrict__ xr4,
            const int4*   __restrict__ idx4,
            const float*  __restrict__ xleft,
            const float*  __restrict__ pos,
            const float*  __restrict__ xr,
            const int*    __restrict__ idx,
            int nq, int E) {
    float local = 0.f;
    for (int t = blockIdx.x * blockDim.x + threadIdx.x; t < nq;
         t += gridDim.x * blockDim.x) {
        float4 a = pos4[3 * t];
        float4 b = pos4[3 * t + 1];
        float4 c = pos4[3 * t + 2];
        float4 w = xr4[t];
        int4  id = idx4[t];
        local += edge_term(a.x, a.y, a.z, w.x, id.x, xleft);
        local += edge_term(a.w, b.x, b.y, w.y, id.y, xleft);
        local += edge_term(b.z, b.w, c.x, w.z, id.z, xleft);
        local += edge_term(c.y, c.z, c.w, w.w, id.w, xleft);
    }
    if (blockIdx.x == 0 && threadIdx.x == 0) {   // tail edges (E % 4)
        for (int e2 = nq * 4; e2 < E; e2++)
            local += edge_term(pos[3 * e2], pos[3 * e2 + 1], pos[3 * e2 + 2],
                               xr[e2], idx[e2], xleft);
    }

    // block reduction -> one double partial per block
    #pragma unroll
    for (int o = 16; o > 0; o >>= 1)
        local += __shfl_down_sync(0xffffffffu, local, o);
    __shared__ float warpsum[8];
    int lane = threadIdx.x & 31, wid = threadIdx.x >> 5;
    if (lane == 0) warpsum[wid] = local;
    __syncthreads();
    if (wid == 0) {
        float v = (lane < 8) ? warpsum[lane] : 0.f;
        #pragma unroll
        for (int o = 4; o > 0; o >>= 1)
            v += __shfl_down_sync(0xffffffffu, v, o);
        if (lane == 0) g_mpart[blockIdx.x] = (double)v;
    }
}

// ---------------------------------------------------------------------------
// Final: fixed-order parallel sums of both partial arrays, then scale.
// ---------------------------------------------------------------------------
__global__ void __launch_bounds__(256) final_kernel(float* __restrict__ out, int nmb) {
    __shared__ double redm[256], redq[256];
    double m = 0.0, q = 0.0;
    for (int i = threadIdx.x; i < nmb; i += 256) m += g_mpart[i];
    for (int i = threadIdx.x; i <= NQB; i += 256) q += (double)g_qpart[i];
    redm[threadIdx.x] = m;
    redq[threadIdx.x] = q;
    __syncthreads();
    #pragma unroll
    for (int s = 128; s > 0; s >>= 1) {
        if (threadIdx.x < s) {
            redm[threadIdx.x] += redm[threadIdx.x + s];
            redq[threadIdx.x] += redq[threadIdx.x + s];
        }
        __syncthreads();
    }
    if (threadIdx.x == 0) {
        double integral = (double)QH * redq[0];
        double cst = 1.0 / sqrt(integral);               // ~1.679 (silu normalize2mom)
        out[0] = (float)(redm[0] * cst);
    }
}

// ---------------------------------------------------------------------------
extern "C" void kernel_launch(void* const* d_in, const int* in_sizes, int n_in,
                              void* d_out, int out_size) {
    const float* pos = (const float*)d_in[0];   // [E,3]
    const float* xr  = (const float*)d_in[1];   // [E,1]
    const float* xl  = (const float*)d_in[2];   // [N,1]
    const float* W1  = (const float*)d_in[3];   // [20,30]
    const float* W2  = (const float*)d_in[4];   // [30,5]
    const int*   oi  = (const int*)d_in[5];     // [E]

    int E = in_sizes[1];          // x_right element count == E
    if (E < 0) E = 0;
    int nq = E / 4;

    setup_kernel<<<NQB + TBLB, SETUP_BT>>>(W1, W2);

    int nb = (nq + 255) / 256;
    if (nb < 1) nb = 1;
    if (nb > MAXMB) nb = MAXMB;
    main_kernel<<<nb, 256>>>((const float4*)pos, (const float4*)xr,
                             (const int4*)oi, xl, pos, xr, oi, nq, E);

    final_kernel<<<1, 256>>>((float*)d_out, nb);
}